// round 11
// baseline (speedup 1.0000x reference)
#include <cuda_runtime.h>
#include <cuda_fp16.h>
#include <math.h>
#include <stdint.h>

// ---------------------------------------------------------------------------
// Problem constants
// ---------------------------------------------------------------------------
#define B_   4
#define S_   2048
#define E_   2048
#define H_   16
#define D_   128
#define MTOT (B_ * S_)

#define NSCALE 4.84480515f                 // sqrt(2*ln(1.25/1e-5))
#define ATTN_SCALE 0.08838834764831845f    // 1/sqrt(128)
#define QSCALE (0.08838834764831845f * 1.4426950408889634f)  // fold log2e

// ---------------------------------------------------------------------------
// Scratch (__device__ globals)
// ---------------------------------------------------------------------------
__device__ __half g_xh[(size_t)MTOT * E_];
__device__ __half g_wh[(size_t)E_ * E_];
__device__ __half g_w3[(size_t)E_ * E_];
__device__ __half g_qh[(size_t)MTOT * E_];
__device__ __half g_kh[(size_t)MTOT * E_];
__device__ __half g_vh[(size_t)MTOT * E_];
__device__ __half g_ch[(size_t)MTOT * E_];
__device__ __half g_cl[(size_t)MTOT * E_];

// ---------------------------------------------------------------------------
// PTX helpers
// ---------------------------------------------------------------------------
__device__ __forceinline__ uint32_t smem_u32(const void* p) {
    uint32_t a;
    asm("{ .reg .u64 t; cvta.to.shared.u64 t, %1; cvt.u32.u64 %0, t; }"
        : "=r"(a) : "l"(p));
    return a;
}

__device__ __forceinline__ void cp16(uint32_t dst, const void* src) {
    asm volatile("cp.async.cg.shared.global [%0], [%1], 16;"
                 :: "r"(dst), "l"(src) : "memory");
}

__device__ __forceinline__ void ldm4(uint32_t* r, uint32_t addr) {
    asm volatile("ldmatrix.sync.aligned.m8n8.x4.shared.b16 {%0,%1,%2,%3}, [%4];"
                 : "=r"(r[0]), "=r"(r[1]), "=r"(r[2]), "=r"(r[3])
                 : "r"(addr));
}

__device__ __forceinline__ void ldm4t(uint32_t* r, uint32_t addr) {
    asm volatile("ldmatrix.sync.aligned.m8n8.x4.trans.shared.b16 {%0,%1,%2,%3}, [%4];"
                 : "=r"(r[0]), "=r"(r[1]), "=r"(r[2]), "=r"(r[3])
                 : "r"(addr));
}

__device__ __forceinline__ void mmah(float* c, const uint32_t* a,
                                     uint32_t b0, uint32_t b1) {
    asm volatile(
        "mma.sync.aligned.m16n8k16.row.col.f32.f16.f16.f32 "
        "{%0,%1,%2,%3}, {%4,%5,%6,%7}, {%8,%9}, {%0,%1,%2,%3};"
        : "+f"(c[0]), "+f"(c[1]), "+f"(c[2]), "+f"(c[3])
        : "r"(a[0]), "r"(a[1]), "r"(a[2]), "r"(a[3]), "r"(b0), "r"(b1));
}

__device__ __forceinline__ float ex2(float x) {
    float r;
    asm("ex2.approx.f32 %0, %1;" : "=f"(r) : "f"(x));
    return r;
}

// ---------------------------------------------------------------------------
// Convert: fp32 -> fp16
// ---------------------------------------------------------------------------
__global__ void convert_h(const float* __restrict__ in,
                          __half* __restrict__ hi, size_t total)
{
    size_t idx = ((size_t)blockIdx.x * blockDim.x + threadIdx.x) * 8;
    if (idx >= total) return;
    float4 a = *(const float4*)(in + idx);
    float4 b = *(const float4*)(in + idx + 4);
    float v[8] = {a.x, a.y, a.z, a.w, b.x, b.y, b.z, b.w};
    __half h8[8];
#pragma unroll
    for (int i = 0; i < 8; i++) h8[i] = __float2half_rn(v[i]);
    *(uint4*)(hi + idx) = *(uint4*)h8;
}

// ---------------------------------------------------------------------------
// 1-term fp16 GEMM-NT + bias (QKV projections), output scaled by outScale.
// ---------------------------------------------------------------------------
#define LDB     80
#define ABYTES  (128 * LDB)
#define STAGE1  (2 * ABYTES)
#define GEMM1_SMEM (3 * STAGE1)
#define KTILES  64

__global__ __launch_bounds__(256, 2)
void gemm1_kernel(const __half* __restrict__ Ah, const __half* __restrict__ Bh,
                  const float* __restrict__ bias, __half* __restrict__ outH,
                  float outScale)
{
    extern __shared__ char smem[];
    const uint32_t sb = smem_u32(smem);
    const int tid  = threadIdx.x;
    const int wid  = tid >> 5;
    const int lane = tid & 31;
    const int nb = blockIdx.x, mb = blockIdx.y;
    const int wm = wid >> 1, wn = wid & 1;

    const __half* pAh = Ah + (size_t)(mb * 128) * 2048;
    const __half* pBh = Bh + (size_t)(nb * 128) * 2048;

    const int lr = tid >> 1;
    const int lc = (tid & 1) * 2;

    auto load_tile = [&](int kt, int buf) {
        const uint32_t s = sb + buf * STAGE1;
        const size_t go = (size_t)lr * 2048 + (size_t)kt * 32 + (size_t)lc * 8;
        const uint32_t so = (uint32_t)lr * LDB + (uint32_t)lc * 16;
#pragma unroll
        for (int j = 0; j < 2; j++) {
            cp16(s + so + j * 16,          pAh + go + j * 8);
            cp16(s + ABYTES + so + j * 16, pBh + go + j * 8);
        }
        asm volatile("cp.async.commit_group;" ::: "memory");
    };

    float acc[2][8][4];
#pragma unroll
    for (int i = 0; i < 2; i++)
#pragma unroll
        for (int j = 0; j < 8; j++)
#pragma unroll
            for (int t = 0; t < 4; t++) acc[i][j][t] = 0.0f;

    const uint32_t aRowOff = (uint32_t)(wm * 32 + (lane & 15)) * LDB
                           + (uint32_t)(lane >> 4) * 16;
    const uint32_t bRowOff = (uint32_t)(wn * 64 + ((lane >> 4) * 8) + (lane & 7)) * LDB
                           + (uint32_t)((lane >> 3) & 1) * 16;

    load_tile(0, 0);
    load_tile(1, 1);
    int buf = 0;

    for (int kt = 0; kt < KTILES; kt++) {
        if (kt + 1 < KTILES) asm volatile("cp.async.wait_group 1;" ::: "memory");
        else                 asm volatile("cp.async.wait_group 0;" ::: "memory");
        __syncthreads();
        if (kt + 2 < KTILES) {
            int nbuf = buf + 2; if (nbuf >= 3) nbuf -= 3;
            load_tile(kt + 2, nbuf);
        }

        const uint32_t aHi = sb + buf * STAGE1;
        const uint32_t bHi = aHi + ABYTES;

#pragma unroll
        for (int ks = 0; ks < 2; ks++) {
            const uint32_t kso = (uint32_t)ks * 32;
            uint32_t ah[2][4];
#pragma unroll
            for (int mf = 0; mf < 2; mf++)
                ldm4(ah[mf], aHi + aRowOff + (uint32_t)mf * 16 * LDB + kso);
#pragma unroll
            for (int nfp = 0; nfp < 4; nfp++) {
                uint32_t bh[4];
                ldm4(bh, bHi + bRowOff + (uint32_t)nfp * 16 * LDB + kso);
#pragma unroll
                for (int p = 0; p < 2; p++) {
                    const int nf = nfp * 2 + p;
#pragma unroll
                    for (int mf = 0; mf < 2; mf++)
                        mmah(acc[mf][nf], ah[mf], bh[2 * p], bh[2 * p + 1]);
                }
            }
        }
        buf++; if (buf >= 3) buf -= 3;
    }

    const int mBase = mb * 128 + wm * 32 + (lane >> 2);
    const int nBase = nb * 128 + wn * 64 + (lane & 3) * 2;
#pragma unroll
    for (int mf = 0; mf < 2; mf++) {
#pragma unroll
        for (int nf = 0; nf < 8; nf++) {
            const int m = mBase + mf * 16;
            const int n = nBase + nf * 8;
            const float2 bb = *(const float2*)(bias + n);
            *(__half2*)(outH + (size_t)m * 2048 + n) = __halves2half2(
                __float2half_rn((acc[mf][nf][0] + bb.x) * outScale),
                __float2half_rn((acc[mf][nf][1] + bb.y) * outScale));
            *(__half2*)(outH + (size_t)(m + 8) * 2048 + n) = __halves2half2(
                __float2half_rn((acc[mf][nf][2] + bb.x) * outScale),
                __float2half_rn((acc[mf][nf][3] + bb.y) * outScale));
        }
    }
}

// ---------------------------------------------------------------------------
// 2-term fp16 GEMM-NT + bias (output projection, fp32 out).
// ---------------------------------------------------------------------------
#define STAGE2  (3 * ABYTES)
#define GEMM2_SMEM (3 * STAGE2)

__global__ __launch_bounds__(256, 2)
void gemm2_kernel(const __half* __restrict__ Ah, const __half* __restrict__ Al,
                  const __half* __restrict__ Bh, const float* __restrict__ bias,
                  float* __restrict__ out)
{
    extern __shared__ char smem[];
    const uint32_t sb = smem_u32(smem);
    const int tid  = threadIdx.x;
    const int wid  = tid >> 5;
    const int lane = tid & 31;
    const int nb = blockIdx.x, mb = blockIdx.y;
    const int wm = wid >> 1, wn = wid & 1;

    const __half* pAh = Ah + (size_t)(mb * 128) * 2048;
    const __half* pAl = Al + (size_t)(mb * 128) * 2048;
    const __half* pBh = Bh + (size_t)(nb * 128) * 2048;

    const int lr = tid >> 1;
    const int lc = (tid & 1) * 2;

    auto load_tile = [&](int kt, int buf) {
        const uint32_t s = sb + buf * STAGE2;
        const size_t go = (size_t)lr * 2048 + (size_t)kt * 32 + (size_t)lc * 8;
        const uint32_t so = (uint32_t)lr * LDB + (uint32_t)lc * 16;
#pragma unroll
        for (int j = 0; j < 2; j++) {
            cp16(s + so + j * 16,              pAh + go + j * 8);
            cp16(s + ABYTES     + so + j * 16, pAl + go + j * 8);
            cp16(s + 2 * ABYTES + so + j * 16, pBh + go + j * 8);
        }
        asm volatile("cp.async.commit_group;" ::: "memory");
    };

    float acc[2][8][4];
#pragma unroll
    for (int i = 0; i < 2; i++)
#pragma unroll
        for (int j = 0; j < 8; j++)
#pragma unroll
            for (int t = 0; t < 4; t++) acc[i][j][t] = 0.0f;

    const uint32_t aRowOff = (uint32_t)(wm * 32 + (lane & 15)) * LDB
                           + (uint32_t)(lane >> 4) * 16;
    const uint32_t bRowOff = (uint32_t)(wn * 64 + ((lane >> 4) * 8) + (lane & 7)) * LDB
                           + (uint32_t)((lane >> 3) & 1) * 16;

    load_tile(0, 0);
    load_tile(1, 1);
    int buf = 0;

    for (int kt = 0; kt < KTILES; kt++) {
        if (kt + 1 < KTILES) asm volatile("cp.async.wait_group 1;" ::: "memory");
        else                 asm volatile("cp.async.wait_group 0;" ::: "memory");
        __syncthreads();
        if (kt + 2 < KTILES) {
            int nbuf = buf + 2; if (nbuf >= 3) nbuf -= 3;
            load_tile(kt + 2, nbuf);
        }

        const uint32_t aHi = sb + buf * STAGE2;
        const uint32_t aLo = aHi + ABYTES;
        const uint32_t bHi = aHi + 2 * ABYTES;

#pragma unroll
        for (int ks = 0; ks < 2; ks++) {
            const uint32_t kso = (uint32_t)ks * 32;
            uint32_t ah[2][4], al[2][4];
#pragma unroll
            for (int mf = 0; mf < 2; mf++) {
                ldm4(ah[mf], aHi + aRowOff + (uint32_t)mf * 16 * LDB + kso);
                ldm4(al[mf], aLo + aRowOff + (uint32_t)mf * 16 * LDB + kso);
            }
#pragma unroll
            for (int nfp = 0; nfp < 4; nfp++) {
                uint32_t bh[4];
                ldm4(bh, bHi + bRowOff + (uint32_t)nfp * 16 * LDB + kso);
#pragma unroll
                for (int p = 0; p < 2; p++) {
                    const int nf = nfp * 2 + p;
#pragma unroll
                    for (int mf = 0; mf < 2; mf++) {
                        mmah(acc[mf][nf], ah[mf], bh[2 * p], bh[2 * p + 1]);
                        mmah(acc[mf][nf], al[mf], bh[2 * p], bh[2 * p + 1]);
                    }
                }
            }
        }
        buf++; if (buf >= 3) buf -= 3;
    }

    const int mBase = mb * 128 + wm * 32 + (lane >> 2);
    const int nBase = nb * 128 + wn * 64 + (lane & 3) * 2;
#pragma unroll
    for (int mf = 0; mf < 2; mf++) {
#pragma unroll
        for (int nf = 0; nf < 8; nf++) {
            const int m = mBase + mf * 16;
            const int n = nBase + nf * 8;
            const float2 bb = *(const float2*)(bias + n);
            *(float2*)(out + (size_t)m * 2048 + n) =
                make_float2(acc[mf][nf][0] + bb.x, acc[mf][nf][1] + bb.y);
            *(float2*)(out + (size_t)(m + 8) * 2048 + n) =
                make_float2(acc[mf][nf][2] + bb.x, acc[mf][nf][3] + bb.y);
        }
    }
}

// ---------------------------------------------------------------------------
// fp16 flash attention, register softmax in exp2 domain (Q pre-scaled),
// 3-stage KV pipeline, alpha-rescale skip when max unchanged.
// ---------------------------------------------------------------------------
#define ALD      272
#define QH_OFF   0
#define KV_OFF   34816
#define KV_STAGE 34816
#define V_O      17408
#define ATTN_SMEM (KV_OFF + 3 * KV_STAGE)   // 139264

__global__ __launch_bounds__(256, 1)
void attn_mma_kernel(const __half* __restrict__ Qh, const __half* __restrict__ Kh,
                     const __half* __restrict__ Vh, const float* __restrict__ Ng,
                     __half* __restrict__ Ohi, __half* __restrict__ Olo)
{
    extern __shared__ char smem[];
    const uint32_t sb = smem_u32(smem);
    const int tid  = threadIdx.x;
    const int wid  = tid >> 5;
    const int lane = tid & 31;

    const int b  = blockIdx.z;
    const int h  = blockIdx.y;
    const int q0 = blockIdx.x * 128;

    const size_t rowg0 = (size_t)b * S_ + q0;
    const size_t brow0 = (size_t)b * S_;
    const size_t hoff  = (size_t)h * D_;

    // ---- load Q tile (pre-scaled by ATTN_SCALE*log2e in projection) ----
    {
        const int r  = tid >> 1;
        const int cb = (tid & 1) * 8;
        const __half* gqh = Qh + (rowg0 + r) * E_ + hoff + cb * 8;
        const uint32_t sq = (uint32_t)r * ALD + (uint32_t)cb * 16;
#pragma unroll
        for (int j = 0; j < 8; j++)
            cp16(sb + QH_OFF + sq + j * 16, gqh + j * 8);
        asm volatile("cp.async.commit_group;" ::: "memory");
    }

    const int kr  = tid >> 2;
    const int kcb = (tid & 3) * 4;
    auto kvload = [&](int t, int buf) {
        const uint32_t s = sb + KV_OFF + buf * KV_STAGE;
        const size_t grow = (brow0 + t * 64 + kr) * E_ + hoff + kcb * 8;
        const uint32_t so = (uint32_t)kr * ALD + (uint32_t)kcb * 16;
#pragma unroll
        for (int j = 0; j < 4; j++) {
            cp16(s + so + j * 16,       Kh + grow + j * 8);
            cp16(s + V_O + so + j * 16, Vh + grow + j * 8);
        }
        asm volatile("cp.async.commit_group;" ::: "memory");
    };

    float acc_o[16][4];
#pragma unroll
    for (int j = 0; j < 16; j++)
#pragma unroll
        for (int t = 0; t < 4; t++) acc_o[j][t] = 0.0f;

    float m0 = -INFINITY, m1 = -INFINITY, l0 = 0.0f, l1 = 0.0f;

    const uint32_t aRowOff = (uint32_t)(wid * 16 + (lane & 15)) * ALD
                           + (uint32_t)(lane >> 4) * 16;
    const uint32_t bRowOff = (uint32_t)(((lane >> 4) * 8) + (lane & 7)) * ALD
                           + (uint32_t)((lane >> 3) & 1) * 16;
    const uint32_t vRowOff = (uint32_t)(lane & 15) * ALD + (uint32_t)(lane >> 4) * 16;

    kvload(0, 0);
    kvload(1, 1);
    const int NT = S_ / 64;

    for (int t = 0; t < NT; t++) {
        int buf = t % 3;
        if (t + 2 < NT) {
            kvload(t + 2, (t + 2) % 3);
            asm volatile("cp.async.wait_group 2;" ::: "memory");
        } else if (t + 1 < NT) {
            asm volatile("cp.async.wait_group 1;" ::: "memory");
        } else {
            asm volatile("cp.async.wait_group 0;" ::: "memory");
        }
        __syncthreads();

        const uint32_t kBase = sb + KV_OFF + buf * KV_STAGE;
        const uint32_t vBase = kBase + V_O;

        // ---- S = Q K^T (scores already in exp2 domain) ----
        float s[8][4];
#pragma unroll
        for (int j = 0; j < 8; j++)
#pragma unroll
            for (int q = 0; q < 4; q++) s[j][q] = 0.0f;

#pragma unroll
        for (int ks = 0; ks < 8; ks++) {
            const uint32_t kso = (uint32_t)ks * 32;
            uint32_t ah[4];
            ldm4(ah, sb + QH_OFF + aRowOff + kso);
#pragma unroll
            for (int nfp = 0; nfp < 4; nfp++) {
                uint32_t bh[4];
                ldm4(bh, kBase + bRowOff + (uint32_t)nfp * 16 * ALD + kso);
                mmah(s[nfp * 2],     ah, bh[0], bh[1]);
                mmah(s[nfp * 2 + 1], ah, bh[2], bh[3]);
            }
        }

        // ---- register softmax (exp2 domain) ----
        float mx0 = -INFINITY, mx1 = -INFINITY;
#pragma unroll
        for (int j = 0; j < 8; j++) {
            mx0 = fmaxf(mx0, fmaxf(s[j][0], s[j][1]));
            mx1 = fmaxf(mx1, fmaxf(s[j][2], s[j][3]));
        }
        mx0 = fmaxf(mx0, __shfl_xor_sync(0xffffffffu, mx0, 1));
        mx0 = fmaxf(mx0, __shfl_xor_sync(0xffffffffu, mx0, 2));
        mx1 = fmaxf(mx1, __shfl_xor_sync(0xffffffffu, mx1, 1));
        mx1 = fmaxf(mx1, __shfl_xor_sync(0xffffffffu, mx1, 2));

        const float mn0 = fmaxf(m0, mx0);
        const float mn1 = fmaxf(m1, mx1);

        float sum0 = 0.0f, sum1 = 0.0f;
        uint32_t pf[4][4];
#pragma unroll
        for (int j = 0; j < 8; j++) {
            s[j][0] = ex2(s[j][0] - mn0);
            s[j][1] = ex2(s[j][1] - mn0);
            s[j][2] = ex2(s[j][2] - mn1);
            s[j][3] = ex2(s[j][3] - mn1);
            sum0 += s[j][0] + s[j][1];
            sum1 += s[j][2] + s[j][3];
        }
#pragma unroll
        for (int k2 = 0; k2 < 4; k2++) {
            const int ja = k2 * 2, jb = k2 * 2 + 1;
            __half2 a0 = __floats2half2_rn(s[ja][0], s[ja][1]);
            __half2 a1 = __floats2half2_rn(s[ja][2], s[ja][3]);
            __half2 a2 = __floats2half2_rn(s[jb][0], s[jb][1]);
            __half2 a3 = __floats2half2_rn(s[jb][2], s[jb][3]);
            pf[k2][0] = *(uint32_t*)&a0;
            pf[k2][1] = *(uint32_t*)&a1;
            pf[k2][2] = *(uint32_t*)&a2;
            pf[k2][3] = *(uint32_t*)&a3;
        }
        sum0 += __shfl_xor_sync(0xffffffffu, sum0, 1);
        sum0 += __shfl_xor_sync(0xffffffffu, sum0, 2);
        sum1 += __shfl_xor_sync(0xffffffffu, sum1, 1);
        sum1 += __shfl_xor_sync(0xffffffffu, sum1, 2);

        if (mn0 != m0 || mn1 != m1) {      // max advanced -> rescale
            const float alpha0 = ex2(m0 - mn0);
            const float alpha1 = ex2(m1 - mn1);
            l0 *= alpha0; l1 *= alpha1;
#pragma unroll
            for (int j = 0; j < 16; j++) {
                acc_o[j][0] *= alpha0; acc_o[j][1] *= alpha0;
                acc_o[j][2] *= alpha1; acc_o[j][3] *= alpha1;
            }
            m0 = mn0; m1 = mn1;
        }
        l0 += sum0;
        l1 += sum1;

        // ---- O += P @ V ----
#pragma unroll
        for (int k2 = 0; k2 < 4; k2++) {
#pragma unroll
            for (int nfp = 0; nfp < 8; nfp++) {
                uint32_t vr[4];
                ldm4t(vr, vBase + vRowOff + (uint32_t)k2 * 16 * ALD
                        + (uint32_t)(nfp * 16) * 2);
                mmah(acc_o[nfp * 2],     pf[k2], vr[0], vr[1]);
                mmah(acc_o[nfp * 2 + 1], pf[k2], vr[2], vr[3]);
            }
        }
        __syncthreads();   // release KV buffer for reuse
    }

    // ---- epilogue: normalize, DP noise, split fp16 hi/lo ----
    const int r0 = wid * 16 + (lane >> 2);
    const float inv0 = 1.0f / l0;
    const float inv1 = 1.0f / l1;
#pragma unroll
    for (int nf = 0; nf < 16; nf++) {
        const int n = nf * 8 + (lane & 3) * 2;
        const size_t g0 = (rowg0 + r0) * E_ + hoff + n;
        const size_t g1 = (rowg0 + r0 + 8) * E_ + hoff + n;
        float2 n0 = *(const float2*)(Ng + g0);
        float2 n1 = *(const float2*)(Ng + g1);
        float v00 = acc_o[nf][0] * inv0 + NSCALE * n0.x;
        float v01 = acc_o[nf][1] * inv0 + NSCALE * n0.y;
        float v10 = acc_o[nf][2] * inv1 + NSCALE * n1.x;
        float v11 = acc_o[nf][3] * inv1 + NSCALE * n1.y;
        __half h00 = __float2half_rn(v00), h01 = __float2half_rn(v01);
        __half h10 = __float2half_rn(v10), h11 = __float2half_rn(v11);
        *(__half2*)(Ohi + g0) = __halves2half2(h00, h01);
        *(__half2*)(Ohi + g1) = __halves2half2(h10, h11);
        *(__half2*)(Olo + g0) = __halves2half2(
            __float2half_rn(v00 - __half2float(h00)),
            __float2half_rn(v01 - __half2float(h01)));
        *(__half2*)(Olo + g1) = __halves2half2(
            __float2half_rn(v10 - __half2float(h10)),
            __float2half_rn(v11 - __half2float(h11)));
    }
}

// ---------------------------------------------------------------------------
// Launch: single-stream linear DAG (R8 structure; fork reverted)
// ---------------------------------------------------------------------------
extern "C" void kernel_launch(void* const* d_in, const int* in_sizes, int n_in,
                              void* d_out, int out_size)
{
    const float* query = (const float*)d_in[0];
    const float* key_t = (const float*)d_in[1];
    const float* value = (const float*)d_in[2];
    const float* Wq    = (const float*)d_in[3];
    const float* bq    = (const float*)d_in[4];
    const float* Wk    = (const float*)d_in[5];
    const float* bk    = (const float*)d_in[6];
    const float* Wv    = (const float*)d_in[7];
    const float* bv    = (const float*)d_in[8];
    const float* Wo    = (const float*)d_in[9];
    const float* bo    = (const float*)d_in[10];
    const float* noise = (const float*)d_in[11];
    float* out = (float*)d_out;

    __half *xh, *wh, *w3, *qh, *kh, *vh, *ch, *cl;
    cudaGetSymbolAddress((void**)&xh, g_xh);
    cudaGetSymbolAddress((void**)&wh, g_wh);
    cudaGetSymbolAddress((void**)&w3, g_w3);
    cudaGetSymbolAddress((void**)&qh, g_qh);
    cudaGetSymbolAddress((void**)&kh, g_kh);
    cudaGetSymbolAddress((void**)&vh, g_vh);
    cudaGetSymbolAddress((void**)&ch, g_ch);
    cudaGetSymbolAddress((void**)&cl, g_cl);

    cudaFuncSetAttribute(gemm1_kernel,
                         cudaFuncAttributeMaxDynamicSharedMemorySize, GEMM1_SMEM);
    cudaFuncSetAttribute(gemm2_kernel,
                         cudaFuncAttributeMaxDynamicSharedMemorySize, GEMM2_SMEM);
    cudaFuncSetAttribute(attn_mma_kernel,
                         cudaFuncAttributeMaxDynamicSharedMemorySize, ATTN_SMEM);

    const size_t xTot = (size_t)MTOT * E_;
    const size_t wTot = (size_t)E_ * E_;
    const int cX = (int)((xTot / 8 + 255) / 256);
    const int cW = (int)((wTot / 8 + 255) / 256);
    dim3 gemmGrid(E_ / 128, MTOT / 128);   // (16, 64)

    // Q = query @ Wq^T + bq  (pre-scaled by ATTN_SCALE*log2e)
    convert_h<<<cX, 256>>>(query, xh, xTot);
    convert_h<<<cW, 256>>>(Wq, wh, wTot);
    gemm1_kernel<<<gemmGrid, 256, GEMM1_SMEM>>>(xh, wh, bq, qh, QSCALE);

    // K = key_t @ Wk^T + bk
    convert_h<<<cX, 256>>>(key_t, xh, xTot);
    convert_h<<<cW, 256>>>(Wk, wh, wTot);
    gemm1_kernel<<<gemmGrid, 256, GEMM1_SMEM>>>(xh, wh, bk, kh, 1.0f);

    // V = value @ Wv^T + bv   (+ Wo convert, independent, fills tail)
    convert_h<<<cX, 256>>>(value, xh, xTot);
    convert_h<<<cW, 256>>>(Wv, wh, wTot);
    convert_h<<<cW, 256>>>(Wo, w3, wTot);
    gemm1_kernel<<<gemmGrid, 256, GEMM1_SMEM>>>(xh, wh, bv, vh, 1.0f);

    // Attention + DP noise -> ctx hi/lo
    dim3 attnGrid(S_ / 128, H_, B_);       // (16, 16, 4)
    attn_mma_kernel<<<attnGrid, 256, ATTN_SMEM>>>(qh, kh, vh, noise, ch, cl);

    // out = ctx @ Wo^T + bo
    gemm2_kernel<<<gemmGrid, 256, GEMM2_SMEM>>>(ch, cl, w3, bo, out);
}

// round 13
// speedup vs baseline: 1.0134x; 1.0134x over previous
#include <cuda_runtime.h>
#include <cuda_fp16.h>
#include <math.h>
#include <stdint.h>

// ---------------------------------------------------------------------------
// Problem constants
// ---------------------------------------------------------------------------
#define B_   4
#define S_   2048
#define E_   2048
#define H_   16
#define D_   128
#define MTOT (B_ * S_)

#define NSCALE 4.84480515f                 // sqrt(2*ln(1.25/1e-5))
#define ATTN_SCALE 0.08838834764831845f    // 1/sqrt(128)

// ---------------------------------------------------------------------------
// Scratch (__device__ globals)
// ---------------------------------------------------------------------------
__device__ __half g_x0[(size_t)MTOT * E_];
__device__ __half g_x1[(size_t)MTOT * E_];
__device__ __half g_x2[(size_t)MTOT * E_];
__device__ __half g_w0[(size_t)E_ * E_];
__device__ __half g_w1[(size_t)E_ * E_];
__device__ __half g_w2[(size_t)E_ * E_];
__device__ __half g_w3[(size_t)E_ * E_];
__device__ __half g_qh[(size_t)MTOT * E_];
__device__ __half g_kh[(size_t)MTOT * E_];
__device__ __half g_vh[(size_t)MTOT * E_];
__device__ __half g_ch[(size_t)MTOT * E_];
__device__ __half g_cl[(size_t)MTOT * E_];

// ---------------------------------------------------------------------------
// Param structs (passed by value; graph-capture safe)
// ---------------------------------------------------------------------------
struct ConvBatch {
    const float* in[4];
    __half* out[4];
};

struct QKVBatch {
    const __half* X[3];
    const __half* W[3];
    const float*  bias[3];
    __half*       out[3];
};

// ---------------------------------------------------------------------------
// PTX helpers
// ---------------------------------------------------------------------------
__device__ __forceinline__ uint32_t smem_u32(const void* p) {
    uint32_t a;
    asm("{ .reg .u64 t; cvta.to.shared.u64 t, %1; cvt.u32.u64 %0, t; }"
        : "=r"(a) : "l"(p));
    return a;
}

__device__ __forceinline__ void cp16(uint32_t dst, const void* src) {
    asm volatile("cp.async.cg.shared.global [%0], [%1], 16;"
                 :: "r"(dst), "l"(src) : "memory");
}

__device__ __forceinline__ void ldm4(uint32_t* r, uint32_t addr) {
    asm volatile("ldmatrix.sync.aligned.m8n8.x4.shared.b16 {%0,%1,%2,%3}, [%4];"
                 : "=r"(r[0]), "=r"(r[1]), "=r"(r[2]), "=r"(r[3])
                 : "r"(addr));
}

__device__ __forceinline__ void ldm4t(uint32_t* r, uint32_t addr) {
    asm volatile("ldmatrix.sync.aligned.m8n8.x4.trans.shared.b16 {%0,%1,%2,%3}, [%4];"
                 : "=r"(r[0]), "=r"(r[1]), "=r"(r[2]), "=r"(r[3])
                 : "r"(addr));
}

__device__ __forceinline__ void mmah(float* c, const uint32_t* a,
                                     uint32_t b0, uint32_t b1) {
    asm volatile(
        "mma.sync.aligned.m16n8k16.row.col.f32.f16.f16.f32 "
        "{%0,%1,%2,%3}, {%4,%5,%6,%7}, {%8,%9}, {%0,%1,%2,%3};"
        : "+f"(c[0]), "+f"(c[1]), "+f"(c[2]), "+f"(c[3])
        : "r"(a[0]), "r"(a[1]), "r"(a[2]), "r"(a[3]), "r"(b0), "r"(b1));
}

// ---------------------------------------------------------------------------
// Batched convert: fp32 -> fp16, blockIdx.y selects tensor
// ---------------------------------------------------------------------------
__global__ void convert_batch(ConvBatch p, size_t total)
{
    const int z = blockIdx.y;
    const float* in = p.in[z];
    __half* out = p.out[z];
    size_t idx = ((size_t)blockIdx.x * blockDim.x + threadIdx.x) * 8;
    if (idx >= total) return;
    float4 a = *(const float4*)(in + idx);
    float4 b = *(const float4*)(in + idx + 4);
    float v[8] = {a.x, a.y, a.z, a.w, b.x, b.y, b.z, b.w};
    __half h8[8];
#pragma unroll
    for (int i = 0; i < 8; i++) h8[i] = __float2half_rn(v[i]);
    *(uint4*)(out + idx) = *(uint4*)h8;
}

// ---------------------------------------------------------------------------
// Batched 1-term fp16 GEMM-NT + bias (QKV projections), blockIdx.z selects
// the (X, W, bias, out) tuple. Mainloop identical to R8's gemm1.
// ---------------------------------------------------------------------------
#define LDB     80
#define ABYTES  (128 * LDB)
#define STAGE1  (2 * ABYTES)
#define GEMM1_SMEM (3 * STAGE1)
#define KTILES  64

__global__ __launch_bounds__(256, 2)
void gemm_qkv_kernel(QKVBatch p)
{
    extern __shared__ char smem[];
    const uint32_t sb = smem_u32(smem);
    const int tid  = threadIdx.x;
    const int wid  = tid >> 5;
    const int lane = tid & 31;
    const int nb = blockIdx.x, mb = blockIdx.y, z = blockIdx.z;
    const int wm = wid >> 1, wn = wid & 1;

    const __half* pAh = p.X[z] + (size_t)(mb * 128) * 2048;
    const __half* pBh = p.W[z] + (size_t)(nb * 128) * 2048;
    const float* bias = p.bias[z];
    __half* outH = p.out[z];

    const int lr = tid >> 1;
    const int lc = (tid & 1) * 2;

    auto load_tile = [&](int kt, int buf) {
        const uint32_t s = sb + buf * STAGE1;
        const size_t go = (size_t)lr * 2048 + (size_t)kt * 32 + (size_t)lc * 8;
        const uint32_t so = (uint32_t)lr * LDB + (uint32_t)lc * 16;
#pragma unroll
        for (int j = 0; j < 2; j++) {
            cp16(s + so + j * 16,          pAh + go + j * 8);
            cp16(s + ABYTES + so + j * 16, pBh + go + j * 8);
        }
        asm volatile("cp.async.commit_group;" ::: "memory");
    };

    float acc[2][8][4];
#pragma unroll
    for (int i = 0; i < 2; i++)
#pragma unroll
        for (int j = 0; j < 8; j++)
#pragma unroll
            for (int t = 0; t < 4; t++) acc[i][j][t] = 0.0f;

    const uint32_t aRowOff = (uint32_t)(wm * 32 + (lane & 15)) * LDB
                           + (uint32_t)(lane >> 4) * 16;
    const uint32_t bRowOff = (uint32_t)(wn * 64 + ((lane >> 4) * 8) + (lane & 7)) * LDB
                           + (uint32_t)((lane >> 3) & 1) * 16;

    load_tile(0, 0);
    load_tile(1, 1);
    int buf = 0;

    for (int kt = 0; kt < KTILES; kt++) {
        if (kt + 1 < KTILES) asm volatile("cp.async.wait_group 1;" ::: "memory");
        else                 asm volatile("cp.async.wait_group 0;" ::: "memory");
        __syncthreads();
        if (kt + 2 < KTILES) {
            int nbuf = buf + 2; if (nbuf >= 3) nbuf -= 3;
            load_tile(kt + 2, nbuf);
        }

        const uint32_t aHi = sb + buf * STAGE1;
        const uint32_t bHi = aHi + ABYTES;

#pragma unroll
        for (int ks = 0; ks < 2; ks++) {
            const uint32_t kso = (uint32_t)ks * 32;
            uint32_t ah[2][4];
#pragma unroll
            for (int mf = 0; mf < 2; mf++)
                ldm4(ah[mf], aHi + aRowOff + (uint32_t)mf * 16 * LDB + kso);
#pragma unroll
            for (int nfp = 0; nfp < 4; nfp++) {
                uint32_t bh[4];
                ldm4(bh, bHi + bRowOff + (uint32_t)nfp * 16 * LDB + kso);
#pragma unroll
                for (int pq = 0; pq < 2; pq++) {
                    const int nf = nfp * 2 + pq;
#pragma unroll
                    for (int mf = 0; mf < 2; mf++)
                        mmah(acc[mf][nf], ah[mf], bh[2 * pq], bh[2 * pq + 1]);
                }
            }
        }
        buf++; if (buf >= 3) buf -= 3;
    }

    const int mBase = mb * 128 + wm * 32 + (lane >> 2);
    const int nBase = nb * 128 + wn * 64 + (lane & 3) * 2;
#pragma unroll
    for (int mf = 0; mf < 2; mf++) {
#pragma unroll
        for (int nf = 0; nf < 8; nf++) {
            const int m = mBase + mf * 16;
            const int n = nBase + nf * 8;
            const float2 bb = *(const float2*)(bias + n);
            *(__half2*)(outH + (size_t)m * 2048 + n) = __halves2half2(
                __float2half_rn(acc[mf][nf][0] + bb.x),
                __float2half_rn(acc[mf][nf][1] + bb.y));
            *(__half2*)(outH + (size_t)(m + 8) * 2048 + n) = __halves2half2(
                __float2half_rn(acc[mf][nf][2] + bb.x),
                __float2half_rn(acc[mf][nf][3] + bb.y));
        }
    }
}

// ---------------------------------------------------------------------------
// 2-term fp16 GEMM-NT + bias (output projection, fp32 out). R8-identical.
// ---------------------------------------------------------------------------
#define STAGE2  (3 * ABYTES)
#define GEMM2_SMEM (3 * STAGE2)

__global__ __launch_bounds__(256, 2)
void gemm2_kernel(const __half* __restrict__ Ah, const __half* __restrict__ Al,
                  const __half* __restrict__ Bh, const float* __restrict__ bias,
                  float* __restrict__ out)
{
    extern __shared__ char smem[];
    const uint32_t sb = smem_u32(smem);
    const int tid  = threadIdx.x;
    const int wid  = tid >> 5;
    const int lane = tid & 31;
    const int nb = blockIdx.x, mb = blockIdx.y;
    const int wm = wid >> 1, wn = wid & 1;

    const __half* pAh = Ah + (size_t)(mb * 128) * 2048;
    const __half* pAl = Al + (size_t)(mb * 128) * 2048;
    const __half* pBh = Bh + (size_t)(nb * 128) * 2048;

    const int lr = tid >> 1;
    const int lc = (tid & 1) * 2;

    auto load_tile = [&](int kt, int buf) {
        const uint32_t s = sb + buf * STAGE2;
        const size_t go = (size_t)lr * 2048 + (size_t)kt * 32 + (size_t)lc * 8;
        const uint32_t so = (uint32_t)lr * LDB + (uint32_t)lc * 16;
#pragma unroll
        for (int j = 0; j < 2; j++) {
            cp16(s + so + j * 16,              pAh + go + j * 8);
            cp16(s + ABYTES     + so + j * 16, pAl + go + j * 8);
            cp16(s + 2 * ABYTES + so + j * 16, pBh + go + j * 8);
        }
        asm volatile("cp.async.commit_group;" ::: "memory");
    };

    float acc[2][8][4];
#pragma unroll
    for (int i = 0; i < 2; i++)
#pragma unroll
        for (int j = 0; j < 8; j++)
#pragma unroll
            for (int t = 0; t < 4; t++) acc[i][j][t] = 0.0f;

    const uint32_t aRowOff = (uint32_t)(wm * 32 + (lane & 15)) * LDB
                           + (uint32_t)(lane >> 4) * 16;
    const uint32_t bRowOff = (uint32_t)(wn * 64 + ((lane >> 4) * 8) + (lane & 7)) * LDB
                           + (uint32_t)((lane >> 3) & 1) * 16;

    load_tile(0, 0);
    load_tile(1, 1);
    int buf = 0;

    for (int kt = 0; kt < KTILES; kt++) {
        if (kt + 1 < KTILES) asm volatile("cp.async.wait_group 1;" ::: "memory");
        else                 asm volatile("cp.async.wait_group 0;" ::: "memory");
        __syncthreads();
        if (kt + 2 < KTILES) {
            int nbuf = buf + 2; if (nbuf >= 3) nbuf -= 3;
            load_tile(kt + 2, nbuf);
        }

        const uint32_t aHi = sb + buf * STAGE2;
        const uint32_t aLo = aHi + ABYTES;
        const uint32_t bHi = aHi + 2 * ABYTES;

#pragma unroll
        for (int ks = 0; ks < 2; ks++) {
            const uint32_t kso = (uint32_t)ks * 32;
            uint32_t ah[2][4], al[2][4];
#pragma unroll
            for (int mf = 0; mf < 2; mf++) {
                ldm4(ah[mf], aHi + aRowOff + (uint32_t)mf * 16 * LDB + kso);
                ldm4(al[mf], aLo + aRowOff + (uint32_t)mf * 16 * LDB + kso);
            }
#pragma unroll
            for (int nfp = 0; nfp < 4; nfp++) {
                uint32_t bh[4];
                ldm4(bh, bHi + bRowOff + (uint32_t)nfp * 16 * LDB + kso);
#pragma unroll
                for (int pq = 0; pq < 2; pq++) {
                    const int nf = nfp * 2 + pq;
#pragma unroll
                    for (int mf = 0; mf < 2; mf++) {
                        mmah(acc[mf][nf], ah[mf], bh[2 * pq], bh[2 * pq + 1]);
                        mmah(acc[mf][nf], al[mf], bh[2 * pq], bh[2 * pq + 1]);
                    }
                }
            }
        }
        buf++; if (buf >= 3) buf -= 3;
    }

    const int mBase = mb * 128 + wm * 32 + (lane >> 2);
    const int nBase = nb * 128 + wn * 64 + (lane & 3) * 2;
#pragma unroll
    for (int mf = 0; mf < 2; mf++) {
#pragma unroll
        for (int nf = 0; nf < 8; nf++) {
            const int m = mBase + mf * 16;
            const int n = nBase + nf * 8;
            const float2 bb = *(const float2*)(bias + n);
            *(float2*)(out + (size_t)m * 2048 + n) =
                make_float2(acc[mf][nf][0] + bb.x, acc[mf][nf][1] + bb.y);
            *(float2*)(out + (size_t)(m + 8) * 2048 + n) =
                make_float2(acc[mf][nf][2] + bb.x, acc[mf][nf][3] + bb.y);
        }
    }
}

// ---------------------------------------------------------------------------
// fp16 flash attention (R8-identical): register softmax, __expf, 2-stage KV.
// ---------------------------------------------------------------------------
#define ALD      272
#define QH_OFF   0
#define KV_OFF   34816
#define KV_STAGE 34816
#define V_O      17408
#define ATTN_SMEM 104448

__global__ __launch_bounds__(256, 1)
void attn_mma_kernel(const __half* __restrict__ Qh, const __half* __restrict__ Kh,
                     const __half* __restrict__ Vh, const float* __restrict__ Ng,
                     __half* __restrict__ Ohi, __half* __restrict__ Olo)
{
    extern __shared__ char smem[];
    const uint32_t sb = smem_u32(smem);
    const int tid  = threadIdx.x;
    const int wid  = tid >> 5;
    const int lane = tid & 31;

    const int b  = blockIdx.z;
    const int h  = blockIdx.y;
    const int q0 = blockIdx.x * 128;

    const size_t rowg0 = (size_t)b * S_ + q0;
    const size_t brow0 = (size_t)b * S_;
    const size_t hoff  = (size_t)h * D_;

    // ---- load Q tile ----
    {
        const int r  = tid >> 1;
        const int cb = (tid & 1) * 8;
        const __half* gqh = Qh + (rowg0 + r) * E_ + hoff + cb * 8;
        const uint32_t sq = (uint32_t)r * ALD + (uint32_t)cb * 16;
#pragma unroll
        for (int j = 0; j < 8; j++)
            cp16(sb + QH_OFF + sq + j * 16, gqh + j * 8);
        asm volatile("cp.async.commit_group;" ::: "memory");
    }

    const int kr  = tid >> 2;
    const int kcb = (tid & 3) * 4;
    auto kvload = [&](int t, int buf) {
        const uint32_t s = sb + KV_OFF + buf * KV_STAGE;
        const size_t grow = (brow0 + t * 64 + kr) * E_ + hoff + kcb * 8;
        const uint32_t so = (uint32_t)kr * ALD + (uint32_t)kcb * 16;
#pragma unroll
        for (int j = 0; j < 4; j++) {
            cp16(s + so + j * 16,       Kh + grow + j * 8);
            cp16(s + V_O + so + j * 16, Vh + grow + j * 8);
        }
        asm volatile("cp.async.commit_group;" ::: "memory");
    };

    float acc_o[16][4];
#pragma unroll
    for (int j = 0; j < 16; j++)
#pragma unroll
        for (int t = 0; t < 4; t++) acc_o[j][t] = 0.0f;

    float m0 = -INFINITY, m1 = -INFINITY, l0 = 0.0f, l1 = 0.0f;

    const uint32_t aRowOff = (uint32_t)(wid * 16 + (lane & 15)) * ALD
                           + (uint32_t)(lane >> 4) * 16;
    const uint32_t bRowOff = (uint32_t)(((lane >> 4) * 8) + (lane & 7)) * ALD
                           + (uint32_t)((lane >> 3) & 1) * 16;
    const uint32_t vRowOff = (uint32_t)(lane & 15) * ALD + (uint32_t)(lane >> 4) * 16;

    kvload(0, 0);

    for (int t = 0; t < S_ / 64; t++) {
        const int buf = t & 1;
        if (t + 1 < S_ / 64) {
            kvload(t + 1, buf ^ 1);
            asm volatile("cp.async.wait_group 1;" ::: "memory");
        } else {
            asm volatile("cp.async.wait_group 0;" ::: "memory");
        }
        __syncthreads();

        const uint32_t kBase = sb + KV_OFF + buf * KV_STAGE;
        const uint32_t vBase = kBase + V_O;

        // ---- S = Q K^T ----
        float s[8][4];
#pragma unroll
        for (int j = 0; j < 8; j++)
#pragma unroll
            for (int q = 0; q < 4; q++) s[j][q] = 0.0f;

#pragma unroll
        for (int ks = 0; ks < 8; ks++) {
            const uint32_t kso = (uint32_t)ks * 32;
            uint32_t ah[4];
            ldm4(ah, sb + QH_OFF + aRowOff + kso);
#pragma unroll
            for (int nfp = 0; nfp < 4; nfp++) {
                uint32_t bh[4];
                ldm4(bh, kBase + bRowOff + (uint32_t)nfp * 16 * ALD + kso);
                mmah(s[nfp * 2],     ah, bh[0], bh[1]);
                mmah(s[nfp * 2 + 1], ah, bh[2], bh[3]);
            }
        }

        // ---- register softmax ----
        float mx0 = -INFINITY, mx1 = -INFINITY;
#pragma unroll
        for (int j = 0; j < 8; j++) {
            s[j][0] *= ATTN_SCALE; s[j][1] *= ATTN_SCALE;
            s[j][2] *= ATTN_SCALE; s[j][3] *= ATTN_SCALE;
            mx0 = fmaxf(mx0, fmaxf(s[j][0], s[j][1]));
            mx1 = fmaxf(mx1, fmaxf(s[j][2], s[j][3]));
        }
        mx0 = fmaxf(mx0, __shfl_xor_sync(0xffffffffu, mx0, 1));
        mx0 = fmaxf(mx0, __shfl_xor_sync(0xffffffffu, mx0, 2));
        mx1 = fmaxf(mx1, __shfl_xor_sync(0xffffffffu, mx1, 1));
        mx1 = fmaxf(mx1, __shfl_xor_sync(0xffffffffu, mx1, 2));

        const float mn0 = fmaxf(m0, mx0);
        const float mn1 = fmaxf(m1, mx1);

        float sum0 = 0.0f, sum1 = 0.0f;
        uint32_t pf[4][4];
#pragma unroll
        for (int j = 0; j < 8; j++) {
            s[j][0] = __expf(s[j][0] - mn0);
            s[j][1] = __expf(s[j][1] - mn0);
            s[j][2] = __expf(s[j][2] - mn1);
            s[j][3] = __expf(s[j][3] - mn1);
            sum0 += s[j][0] + s[j][1];
            sum1 += s[j][2] + s[j][3];
        }
#pragma unroll
        for (int k2 = 0; k2 < 4; k2++) {
            const int ja = k2 * 2, jb = k2 * 2 + 1;
            __half2 a0 = __floats2half2_rn(s[ja][0], s[ja][1]);
            __half2 a1 = __floats2half2_rn(s[ja][2], s[ja][3]);
            __half2 a2 = __floats2half2_rn(s[jb][0], s[jb][1]);
            __half2 a3 = __floats2half2_rn(s[jb][2], s[jb][3]);
            pf[k2][0] = *(uint32_t*)&a0;
            pf[k2][1] = *(uint32_t*)&a1;
            pf[k2][2] = *(uint32_t*)&a2;
            pf[k2][3] = *(uint32_t*)&a3;
        }
        sum0 += __shfl_xor_sync(0xffffffffu, sum0, 1);
        sum0 += __shfl_xor_sync(0xffffffffu, sum0, 2);
        sum1 += __shfl_xor_sync(0xffffffffu, sum1, 1);
        sum1 += __shfl_xor_sync(0xffffffffu, sum1, 2);

        const float alpha0 = __expf(m0 - mn0);
        const float alpha1 = __expf(m1 - mn1);
        m0 = mn0; m1 = mn1;
        l0 = l0 * alpha0 + sum0;
        l1 = l1 * alpha1 + sum1;

        // ---- rescale O ----
#pragma unroll
        for (int j = 0; j < 16; j++) {
            acc_o[j][0] *= alpha0; acc_o[j][1] *= alpha0;
            acc_o[j][2] *= alpha1; acc_o[j][3] *= alpha1;
        }

        // ---- O += P @ V ----
#pragma unroll
        for (int k2 = 0; k2 < 4; k2++) {
#pragma unroll
            for (int nfp = 0; nfp < 8; nfp++) {
                uint32_t vr[4];
                ldm4t(vr, vBase + vRowOff + (uint32_t)k2 * 16 * ALD
                        + (uint32_t)(nfp * 16) * 2);
                mmah(acc_o[nfp * 2],     pf[k2], vr[0], vr[1]);
                mmah(acc_o[nfp * 2 + 1], pf[k2], vr[2], vr[3]);
            }
        }
        __syncthreads();   // release KV buffer before next prefetch overwrites
    }

    // ---- epilogue: normalize, DP noise, split fp16 hi/lo ----
    const int r0 = wid * 16 + (lane >> 2);
    const float inv0 = 1.0f / l0;
    const float inv1 = 1.0f / l1;
#pragma unroll
    for (int nf = 0; nf < 16; nf++) {
        const int n = nf * 8 + (lane & 3) * 2;
        const size_t g0 = (rowg0 + r0) * E_ + hoff + n;
        const size_t g1 = (rowg0 + r0 + 8) * E_ + hoff + n;
        float2 n0 = *(const float2*)(Ng + g0);
        float2 n1 = *(const float2*)(Ng + g1);
        float v00 = acc_o[nf][0] * inv0 + NSCALE * n0.x;
        float v01 = acc_o[nf][1] * inv0 + NSCALE * n0.y;
        float v10 = acc_o[nf][2] * inv1 + NSCALE * n1.x;
        float v11 = acc_o[nf][3] * inv1 + NSCALE * n1.y;
        __half h00 = __float2half_rn(v00), h01 = __float2half_rn(v01);
        __half h10 = __float2half_rn(v10), h11 = __float2half_rn(v11);
        *(__half2*)(Ohi + g0) = __halves2half2(h00, h01);
        *(__half2*)(Ohi + g1) = __halves2half2(h10, h11);
        *(__half2*)(Olo + g0) = __halves2half2(
            __float2half_rn(v00 - __half2float(h00)),
            __float2half_rn(v01 - __half2float(h01)));
        *(__half2*)(Olo + g1) = __halves2half2(
            __float2half_rn(v10 - __half2float(h10)),
            __float2half_rn(v11 - __half2float(h11)));
    }
}

// ---------------------------------------------------------------------------
// Launch: 5 launches — convX(3-batch), convW(4-batch), gemmQKV(3-batch),
// attention, output GEMM.
// ---------------------------------------------------------------------------
extern "C" void kernel_launch(void* const* d_in, const int* in_sizes, int n_in,
                              void* d_out, int out_size)
{
    const float* query = (const float*)d_in[0];
    const float* key_t = (const float*)d_in[1];
    const float* value = (const float*)d_in[2];
    const float* Wq    = (const float*)d_in[3];
    const float* bq    = (const float*)d_in[4];
    const float* Wk    = (const float*)d_in[5];
    const float* bk    = (const float*)d_in[6];
    const float* Wv    = (const float*)d_in[7];
    const float* bv    = (const float*)d_in[8];
    const float* Wo    = (const float*)d_in[9];
    const float* bo    = (const float*)d_in[10];
    const float* noise = (const float*)d_in[11];
    float* out = (float*)d_out;

    __half *x0, *x1, *x2, *w0, *w1, *w2, *w3, *qh, *kh, *vh, *ch, *cl;
    cudaGetSymbolAddress((void**)&x0, g_x0);
    cudaGetSymbolAddress((void**)&x1, g_x1);
    cudaGetSymbolAddress((void**)&x2, g_x2);
    cudaGetSymbolAddress((void**)&w0, g_w0);
    cudaGetSymbolAddress((void**)&w1, g_w1);
    cudaGetSymbolAddress((void**)&w2, g_w2);
    cudaGetSymbolAddress((void**)&w3, g_w3);
    cudaGetSymbolAddress((void**)&qh, g_qh);
    cudaGetSymbolAddress((void**)&kh, g_kh);
    cudaGetSymbolAddress((void**)&vh, g_vh);
    cudaGetSymbolAddress((void**)&ch, g_ch);
    cudaGetSymbolAddress((void**)&cl, g_cl);

    cudaFuncSetAttribute(gemm_qkv_kernel,
                         cudaFuncAttributeMaxDynamicSharedMemorySize, GEMM1_SMEM);
    cudaFuncSetAttribute(gemm2_kernel,
                         cudaFuncAttributeMaxDynamicSharedMemorySize, GEMM2_SMEM);
    cudaFuncSetAttribute(attn_mma_kernel,
                         cudaFuncAttributeMaxDynamicSharedMemorySize, ATTN_SMEM);

    const size_t xTot = (size_t)MTOT * E_;
    const size_t wTot = (size_t)E_ * E_;
    const int cX = (int)((xTot / 8 + 255) / 256);
    const int cW = (int)((wTot / 8 + 255) / 256);

    // batched converts
    ConvBatch cbx;
    cbx.in[0] = query; cbx.out[0] = x0;
    cbx.in[1] = key_t; cbx.out[1] = x1;
    cbx.in[2] = value; cbx.out[2] = x2;
    cbx.in[3] = nullptr; cbx.out[3] = nullptr;
    convert_batch<<<dim3(cX, 3), 256>>>(cbx, xTot);

    ConvBatch cbw;
    cbw.in[0] = Wq; cbw.out[0] = w0;
    cbw.in[1] = Wk; cbw.out[1] = w1;
    cbw.in[2] = Wv; cbw.out[2] = w2;
    cbw.in[3] = Wo; cbw.out[3] = w3;
    convert_batch<<<dim3(cW, 4), 256>>>(cbw, wTot);

    // batched QKV projections
    QKVBatch qp;
    qp.X[0] = x0; qp.W[0] = w0; qp.bias[0] = bq; qp.out[0] = qh;
    qp.X[1] = x1; qp.W[1] = w1; qp.bias[1] = bk; qp.out[1] = kh;
    qp.X[2] = x2; qp.W[2] = w2; qp.bias[2] = bv; qp.out[2] = vh;
    gemm_qkv_kernel<<<dim3(E_ / 128, MTOT / 128, 3), 256, GEMM1_SMEM>>>(qp);

    // Attention + DP noise -> ctx hi/lo
    dim3 attnGrid(S_ / 128, H_, B_);       // (16, 16, 4)
    attn_mma_kernel<<<attnGrid, 256, ATTN_SMEM>>>(qh, kh, vh, noise, ch, cl);

    // out = ctx @ Wo^T + bo
    gemm2_kernel<<<dim3(E_ / 128, MTOT / 128), 256, GEMM2_SMEM>>>(ch, cl, w3, bo, out);
}

// round 14
// speedup vs baseline: 1.0329x; 1.0193x over previous
#include <cuda_runtime.h>
#include <cuda_fp16.h>
#include <math.h>
#include <stdint.h>

// ---------------------------------------------------------------------------
// Problem constants
// ---------------------------------------------------------------------------
#define B_   4
#define S_   2048
#define E_   2048
#define H_   16
#define D_   128
#define MTOT (B_ * S_)

#define NSCALE 4.84480515f                 // sqrt(2*ln(1.25/1e-5))
#define ATTN_SCALE 0.08838834764831845f    // 1/sqrt(128)

// ---------------------------------------------------------------------------
// Scratch (__device__ globals)
// ---------------------------------------------------------------------------
__device__ __half g_x0[(size_t)MTOT * E_];
__device__ __half g_x1[(size_t)MTOT * E_];
__device__ __half g_x2[(size_t)MTOT * E_];
__device__ __half g_w0[(size_t)E_ * E_];
__device__ __half g_w1[(size_t)E_ * E_];
__device__ __half g_w2[(size_t)E_ * E_];
__device__ __half g_w3[(size_t)E_ * E_];
__device__ __half g_qh[(size_t)MTOT * E_];
__device__ __half g_kh[(size_t)MTOT * E_];
__device__ __half g_vh[(size_t)MTOT * E_];
__device__ __half g_ch[(size_t)MTOT * E_];
__device__ __half g_cl[(size_t)MTOT * E_];

// ---------------------------------------------------------------------------
// Param structs (passed by value; graph-capture safe)
// ---------------------------------------------------------------------------
struct ConvBatch {
    const float* in[4];
    __half* out[4];
};

struct QKVBatch {
    const __half* X[3];
    const __half* W[3];
    const float*  bias[3];
    __half*       out[3];
};

// ---------------------------------------------------------------------------
// PTX helpers
// ---------------------------------------------------------------------------
__device__ __forceinline__ uint32_t smem_u32(const void* p) {
    uint32_t a;
    asm("{ .reg .u64 t; cvta.to.shared.u64 t, %1; cvt.u32.u64 %0, t; }"
        : "=r"(a) : "l"(p));
    return a;
}

__device__ __forceinline__ void cp16(uint32_t dst, const void* src) {
    asm volatile("cp.async.cg.shared.global [%0], [%1], 16;"
                 :: "r"(dst), "l"(src) : "memory");
}

__device__ __forceinline__ void ldm4(uint32_t* r, uint32_t addr) {
    asm volatile("ldmatrix.sync.aligned.m8n8.x4.shared.b16 {%0,%1,%2,%3}, [%4];"
                 : "=r"(r[0]), "=r"(r[1]), "=r"(r[2]), "=r"(r[3])
                 : "r"(addr));
}

__device__ __forceinline__ void ldm4t(uint32_t* r, uint32_t addr) {
    asm volatile("ldmatrix.sync.aligned.m8n8.x4.trans.shared.b16 {%0,%1,%2,%3}, [%4];"
                 : "=r"(r[0]), "=r"(r[1]), "=r"(r[2]), "=r"(r[3])
                 : "r"(addr));
}

__device__ __forceinline__ void mmah(float* c, const uint32_t* a,
                                     uint32_t b0, uint32_t b1) {
    asm volatile(
        "mma.sync.aligned.m16n8k16.row.col.f32.f16.f16.f32 "
        "{%0,%1,%2,%3}, {%4,%5,%6,%7}, {%8,%9}, {%0,%1,%2,%3};"
        : "+f"(c[0]), "+f"(c[1]), "+f"(c[2]), "+f"(c[3])
        : "r"(a[0]), "r"(a[1]), "r"(a[2]), "r"(a[3]), "r"(b0), "r"(b1));
}

// ---------------------------------------------------------------------------
// Batched convert: fp32 -> fp16, blockIdx.y selects tensor
// ---------------------------------------------------------------------------
__global__ void convert_batch(ConvBatch p, size_t total)
{
    const int z = blockIdx.y;
    const float* in = p.in[z];
    __half* out = p.out[z];
    size_t idx = ((size_t)blockIdx.x * blockDim.x + threadIdx.x) * 8;
    if (idx >= total) return;
    float4 a = *(const float4*)(in + idx);
    float4 b = *(const float4*)(in + idx + 4);
    float v[8] = {a.x, a.y, a.z, a.w, b.x, b.y, b.z, b.w};
    __half h8[8];
#pragma unroll
    for (int i = 0; i < 8; i++) h8[i] = __float2half_rn(v[i]);
    *(uint4*)(out + idx) = *(uint4*)h8;
}

// ---------------------------------------------------------------------------
// Batched 1-term fp16 GEMM-NT + bias (QKV projections), blockIdx.z selects
// the (X, W, bias, out) tuple.
// ---------------------------------------------------------------------------
#define LDB     80
#define ABYTES  (128 * LDB)
#define STAGE1  (2 * ABYTES)
#define GEMM1_SMEM (3 * STAGE1)
#define KTILES  64

__global__ __launch_bounds__(256, 2)
void gemm_qkv_kernel(QKVBatch p)
{
    extern __shared__ char smem[];
    const uint32_t sb = smem_u32(smem);
    const int tid  = threadIdx.x;
    const int wid  = tid >> 5;
    const int lane = tid & 31;
    const int nb = blockIdx.x, mb = blockIdx.y, z = blockIdx.z;
    const int wm = wid >> 1, wn = wid & 1;

    const __half* pAh = p.X[z] + (size_t)(mb * 128) * 2048;
    const __half* pBh = p.W[z] + (size_t)(nb * 128) * 2048;
    const float* bias = p.bias[z];
    __half* outH = p.out[z];

    const int lr = tid >> 1;
    const int lc = (tid & 1) * 2;

    auto load_tile = [&](int kt, int buf) {
        const uint32_t s = sb + buf * STAGE1;
        const size_t go = (size_t)lr * 2048 + (size_t)kt * 32 + (size_t)lc * 8;
        const uint32_t so = (uint32_t)lr * LDB + (uint32_t)lc * 16;
#pragma unroll
        for (int j = 0; j < 2; j++) {
            cp16(s + so + j * 16,          pAh + go + j * 8);
            cp16(s + ABYTES + so + j * 16, pBh + go + j * 8);
        }
        asm volatile("cp.async.commit_group;" ::: "memory");
    };

    float acc[2][8][4];
#pragma unroll
    for (int i = 0; i < 2; i++)
#pragma unroll
        for (int j = 0; j < 8; j++)
#pragma unroll
            for (int t = 0; t < 4; t++) acc[i][j][t] = 0.0f;

    const uint32_t aRowOff = (uint32_t)(wm * 32 + (lane & 15)) * LDB
                           + (uint32_t)(lane >> 4) * 16;
    const uint32_t bRowOff = (uint32_t)(wn * 64 + ((lane >> 4) * 8) + (lane & 7)) * LDB
                           + (uint32_t)((lane >> 3) & 1) * 16;

    load_tile(0, 0);
    load_tile(1, 1);
    int buf = 0;

    for (int kt = 0; kt < KTILES; kt++) {
        if (kt + 1 < KTILES) asm volatile("cp.async.wait_group 1;" ::: "memory");
        else                 asm volatile("cp.async.wait_group 0;" ::: "memory");
        __syncthreads();
        if (kt + 2 < KTILES) {
            int nbuf = buf + 2; if (nbuf >= 3) nbuf -= 3;
            load_tile(kt + 2, nbuf);
        }

        const uint32_t aHi = sb + buf * STAGE1;
        const uint32_t bHi = aHi + ABYTES;

#pragma unroll
        for (int ks = 0; ks < 2; ks++) {
            const uint32_t kso = (uint32_t)ks * 32;
            uint32_t ah[2][4];
#pragma unroll
            for (int mf = 0; mf < 2; mf++)
                ldm4(ah[mf], aHi + aRowOff + (uint32_t)mf * 16 * LDB + kso);
#pragma unroll
            for (int nfp = 0; nfp < 4; nfp++) {
                uint32_t bh[4];
                ldm4(bh, bHi + bRowOff + (uint32_t)nfp * 16 * LDB + kso);
#pragma unroll
                for (int pq = 0; pq < 2; pq++) {
                    const int nf = nfp * 2 + pq;
#pragma unroll
                    for (int mf = 0; mf < 2; mf++)
                        mmah(acc[mf][nf], ah[mf], bh[2 * pq], bh[2 * pq + 1]);
                }
            }
        }
        buf++; if (buf >= 3) buf -= 3;
    }

    const int mBase = mb * 128 + wm * 32 + (lane >> 2);
    const int nBase = nb * 128 + wn * 64 + (lane & 3) * 2;
#pragma unroll
    for (int mf = 0; mf < 2; mf++) {
#pragma unroll
        for (int nf = 0; nf < 8; nf++) {
            const int m = mBase + mf * 16;
            const int n = nBase + nf * 8;
            const float2 bb = *(const float2*)(bias + n);
            *(__half2*)(outH + (size_t)m * 2048 + n) = __halves2half2(
                __float2half_rn(acc[mf][nf][0] + bb.x),
                __float2half_rn(acc[mf][nf][1] + bb.y));
            *(__half2*)(outH + (size_t)(m + 8) * 2048 + n) = __halves2half2(
                __float2half_rn(acc[mf][nf][2] + bb.x),
                __float2half_rn(acc[mf][nf][3] + bb.y));
        }
    }
}

// ---------------------------------------------------------------------------
// 2-term fp16 GEMM-NT + bias (output projection, fp32 out).
// ---------------------------------------------------------------------------
#define STAGE2  (3 * ABYTES)
#define GEMM2_SMEM (3 * STAGE2)

__global__ __launch_bounds__(256, 2)
void gemm2_kernel(const __half* __restrict__ Ah, const __half* __restrict__ Al,
                  const __half* __restrict__ Bh, const float* __restrict__ bias,
                  float* __restrict__ out)
{
    extern __shared__ char smem[];
    const uint32_t sb = smem_u32(smem);
    const int tid  = threadIdx.x;
    const int wid  = tid >> 5;
    const int lane = tid & 31;
    const int nb = blockIdx.x, mb = blockIdx.y;
    const int wm = wid >> 1, wn = wid & 1;

    const __half* pAh = Ah + (size_t)(mb * 128) * 2048;
    const __half* pAl = Al + (size_t)(mb * 128) * 2048;
    const __half* pBh = Bh + (size_t)(nb * 128) * 2048;

    const int lr = tid >> 1;
    const int lc = (tid & 1) * 2;

    auto load_tile = [&](int kt, int buf) {
        const uint32_t s = sb + buf * STAGE2;
        const size_t go = (size_t)lr * 2048 + (size_t)kt * 32 + (size_t)lc * 8;
        const uint32_t so = (uint32_t)lr * LDB + (uint32_t)lc * 16;
#pragma unroll
        for (int j = 0; j < 2; j++) {
            cp16(s + so + j * 16,              pAh + go + j * 8);
            cp16(s + ABYTES     + so + j * 16, pAl + go + j * 8);
            cp16(s + 2 * ABYTES + so + j * 16, pBh + go + j * 8);
        }
        asm volatile("cp.async.commit_group;" ::: "memory");
    };

    float acc[2][8][4];
#pragma unroll
    for (int i = 0; i < 2; i++)
#pragma unroll
        for (int j = 0; j < 8; j++)
#pragma unroll
            for (int t = 0; t < 4; t++) acc[i][j][t] = 0.0f;

    const uint32_t aRowOff = (uint32_t)(wm * 32 + (lane & 15)) * LDB
                           + (uint32_t)(lane >> 4) * 16;
    const uint32_t bRowOff = (uint32_t)(wn * 64 + ((lane >> 4) * 8) + (lane & 7)) * LDB
                           + (uint32_t)((lane >> 3) & 1) * 16;

    load_tile(0, 0);
    load_tile(1, 1);
    int buf = 0;

    for (int kt = 0; kt < KTILES; kt++) {
        if (kt + 1 < KTILES) asm volatile("cp.async.wait_group 1;" ::: "memory");
        else                 asm volatile("cp.async.wait_group 0;" ::: "memory");
        __syncthreads();
        if (kt + 2 < KTILES) {
            int nbuf = buf + 2; if (nbuf >= 3) nbuf -= 3;
            load_tile(kt + 2, nbuf);
        }

        const uint32_t aHi = sb + buf * STAGE2;
        const uint32_t aLo = aHi + ABYTES;
        const uint32_t bHi = aHi + 2 * ABYTES;

#pragma unroll
        for (int ks = 0; ks < 2; ks++) {
            const uint32_t kso = (uint32_t)ks * 32;
            uint32_t ah[2][4], al[2][4];
#pragma unroll
            for (int mf = 0; mf < 2; mf++) {
                ldm4(ah[mf], aHi + aRowOff + (uint32_t)mf * 16 * LDB + kso);
                ldm4(al[mf], aLo + aRowOff + (uint32_t)mf * 16 * LDB + kso);
            }
#pragma unroll
            for (int nfp = 0; nfp < 4; nfp++) {
                uint32_t bh[4];
                ldm4(bh, bHi + bRowOff + (uint32_t)nfp * 16 * LDB + kso);
#pragma unroll
                for (int pq = 0; pq < 2; pq++) {
                    const int nf = nfp * 2 + pq;
#pragma unroll
                    for (int mf = 0; mf < 2; mf++) {
                        mmah(acc[mf][nf], ah[mf], bh[2 * pq], bh[2 * pq + 1]);
                        mmah(acc[mf][nf], al[mf], bh[2 * pq], bh[2 * pq + 1]);
                    }
                }
            }
        }
        buf++; if (buf >= 3) buf -= 3;
    }

    const int mBase = mb * 128 + wm * 32 + (lane >> 2);
    const int nBase = nb * 128 + wn * 64 + (lane & 3) * 2;
#pragma unroll
    for (int mf = 0; mf < 2; mf++) {
#pragma unroll
        for (int nf = 0; nf < 8; nf++) {
            const int m = mBase + mf * 16;
            const int n = nBase + nf * 8;
            const float2 bb = *(const float2*)(bias + n);
            *(float2*)(out + (size_t)m * 2048 + n) =
                make_float2(acc[mf][nf][0] + bb.x, acc[mf][nf][1] + bb.y);
            *(float2*)(out + (size_t)(m + 8) * 2048 + n) =
                make_float2(acc[mf][nf][2] + bb.x, acc[mf][nf][3] + bb.y);
        }
    }
}

// ---------------------------------------------------------------------------
// fp16 flash attention. Same math as R8/R12; register pressure reduced
// (inline P-fragment packing) and __launch_bounds__(256,2) -> 2 CTAs/SM.
// ---------------------------------------------------------------------------
#define ALD      272
#define QH_OFF   0
#define KV_OFF   34816
#define KV_STAGE 34816
#define V_O      17408
#define ATTN_SMEM 104448

__global__ __launch_bounds__(256, 2)
void attn_mma_kernel(const __half* __restrict__ Qh, const __half* __restrict__ Kh,
                     const __half* __restrict__ Vh, const float* __restrict__ Ng,
                     __half* __restrict__ Ohi, __half* __restrict__ Olo)
{
    extern __shared__ char smem[];
    const uint32_t sb = smem_u32(smem);
    const int tid  = threadIdx.x;
    const int wid  = tid >> 5;
    const int lane = tid & 31;

    const int b  = blockIdx.z;
    const int h  = blockIdx.y;
    const int q0 = blockIdx.x * 128;

    const size_t rowg0 = (size_t)b * S_ + q0;
    const size_t brow0 = (size_t)b * S_;
    const size_t hoff  = (size_t)h * D_;

    // ---- load Q tile ----
    {
        const int r  = tid >> 1;
        const int cb = (tid & 1) * 8;
        const __half* gqh = Qh + (rowg0 + r) * E_ + hoff + cb * 8;
        const uint32_t sq = (uint32_t)r * ALD + (uint32_t)cb * 16;
#pragma unroll
        for (int j = 0; j < 8; j++)
            cp16(sb + QH_OFF + sq + j * 16, gqh + j * 8);
        asm volatile("cp.async.commit_group;" ::: "memory");
    }

    const int kr  = tid >> 2;
    const int kcb = (tid & 3) * 4;
    auto kvload = [&](int t, int buf) {
        const uint32_t s = sb + KV_OFF + buf * KV_STAGE;
        const size_t grow = (brow0 + t * 64 + kr) * E_ + hoff + kcb * 8;
        const uint32_t so = (uint32_t)kr * ALD + (uint32_t)kcb * 16;
#pragma unroll
        for (int j = 0; j < 4; j++) {
            cp16(s + so + j * 16,       Kh + grow + j * 8);
            cp16(s + V_O + so + j * 16, Vh + grow + j * 8);
        }
        asm volatile("cp.async.commit_group;" ::: "memory");
    };

    float acc_o[16][4];
#pragma unroll
    for (int j = 0; j < 16; j++)
#pragma unroll
        for (int t = 0; t < 4; t++) acc_o[j][t] = 0.0f;

    float m0 = -INFINITY, m1 = -INFINITY, l0 = 0.0f, l1 = 0.0f;

    const uint32_t aRowOff = (uint32_t)(wid * 16 + (lane & 15)) * ALD
                           + (uint32_t)(lane >> 4) * 16;
    const uint32_t bRowOff = (uint32_t)(((lane >> 4) * 8) + (lane & 7)) * ALD
                           + (uint32_t)((lane >> 3) & 1) * 16;
    const uint32_t vRowOff = (uint32_t)(lane & 15) * ALD + (uint32_t)(lane >> 4) * 16;

    kvload(0, 0);

    for (int t = 0; t < S_ / 64; t++) {
        const int buf = t & 1;
        if (t + 1 < S_ / 64) {
            kvload(t + 1, buf ^ 1);
            asm volatile("cp.async.wait_group 1;" ::: "memory");
        } else {
            asm volatile("cp.async.wait_group 0;" ::: "memory");
        }
        __syncthreads();

        const uint32_t kBase = sb + KV_OFF + buf * KV_STAGE;
        const uint32_t vBase = kBase + V_O;

        // ---- S = Q K^T ----
        float s[8][4];
#pragma unroll
        for (int j = 0; j < 8; j++)
#pragma unroll
            for (int q = 0; q < 4; q++) s[j][q] = 0.0f;

#pragma unroll
        for (int ks = 0; ks < 8; ks++) {
            const uint32_t kso = (uint32_t)ks * 32;
            uint32_t ah[4];
            ldm4(ah, sb + QH_OFF + aRowOff + kso);
#pragma unroll
            for (int nfp = 0; nfp < 4; nfp++) {
                uint32_t bh[4];
                ldm4(bh, kBase + bRowOff + (uint32_t)nfp * 16 * ALD + kso);
                mmah(s[nfp * 2],     ah, bh[0], bh[1]);
                mmah(s[nfp * 2 + 1], ah, bh[2], bh[3]);
            }
        }

        // ---- register softmax ----
        float mx0 = -INFINITY, mx1 = -INFINITY;
#pragma unroll
        for (int j = 0; j < 8; j++) {
            s[j][0] *= ATTN_SCALE; s[j][1] *= ATTN_SCALE;
            s[j][2] *= ATTN_SCALE; s[j][3] *= ATTN_SCALE;
            mx0 = fmaxf(mx0, fmaxf(s[j][0], s[j][1]));
            mx1 = fmaxf(mx1, fmaxf(s[j][2], s[j][3]));
        }
        mx0 = fmaxf(mx0, __shfl_xor_sync(0xffffffffu, mx0, 1));
        mx0 = fmaxf(mx0, __shfl_xor_sync(0xffffffffu, mx0, 2));
        mx1 = fmaxf(mx1, __shfl_xor_sync(0xffffffffu, mx1, 1));
        mx1 = fmaxf(mx1, __shfl_xor_sync(0xffffffffu, mx1, 2));

        const float mn0 = fmaxf(m0, mx0);
        const float mn1 = fmaxf(m1, mx1);

        float sum0 = 0.0f, sum1 = 0.0f;
#pragma unroll
        for (int j = 0; j < 8; j++) {
            s[j][0] = __expf(s[j][0] - mn0);
            s[j][1] = __expf(s[j][1] - mn0);
            s[j][2] = __expf(s[j][2] - mn1);
            s[j][3] = __expf(s[j][3] - mn1);
            sum0 += s[j][0] + s[j][1];
            sum1 += s[j][2] + s[j][3];
        }
        sum0 += __shfl_xor_sync(0xffffffffu, sum0, 1);
        sum0 += __shfl_xor_sync(0xffffffffu, sum0, 2);
        sum1 += __shfl_xor_sync(0xffffffffu, sum1, 1);
        sum1 += __shfl_xor_sync(0xffffffffu, sum1, 2);

        const float alpha0 = __expf(m0 - mn0);
        const float alpha1 = __expf(m1 - mn1);
        m0 = mn0; m1 = mn1;
        l0 = l0 * alpha0 + sum0;
        l1 = l1 * alpha1 + sum1;

        // ---- rescale O ----
#pragma unroll
        for (int j = 0; j < 16; j++) {
            acc_o[j][0] *= alpha0; acc_o[j][1] *= alpha0;
            acc_o[j][2] *= alpha1; acc_o[j][3] *= alpha1;
        }

        // ---- O += P @ V (P a-frags packed inline to cut live registers) ----
#pragma unroll
        for (int k2 = 0; k2 < 4; k2++) {
            const int ja = k2 * 2, jb = k2 * 2 + 1;
            uint32_t pf[4];
            {
                __half2 a0 = __floats2half2_rn(s[ja][0], s[ja][1]);
                __half2 a1 = __floats2half2_rn(s[ja][2], s[ja][3]);
                __half2 a2 = __floats2half2_rn(s[jb][0], s[jb][1]);
                __half2 a3 = __floats2half2_rn(s[jb][2], s[jb][3]);
                pf[0] = *(uint32_t*)&a0;
                pf[1] = *(uint32_t*)&a1;
                pf[2] = *(uint32_t*)&a2;
                pf[3] = *(uint32_t*)&a3;
            }
#pragma unroll
            for (int nfp = 0; nfp < 8; nfp++) {
                uint32_t vr[4];
                ldm4t(vr, vBase + vRowOff + (uint32_t)k2 * 16 * ALD
                        + (uint32_t)(nfp * 16) * 2);
                mmah(acc_o[nfp * 2],     pf, vr[0], vr[1]);
                mmah(acc_o[nfp * 2 + 1], pf, vr[2], vr[3]);
            }
        }
        __syncthreads();   // release KV buffer before next prefetch overwrites
    }

    // ---- epilogue: normalize, DP noise, split fp16 hi/lo ----
    const int r0 = wid * 16 + (lane >> 2);
    const float inv0 = 1.0f / l0;
    const float inv1 = 1.0f / l1;
#pragma unroll
    for (int nf = 0; nf < 16; nf++) {
        const int n = nf * 8 + (lane & 3) * 2;
        const size_t g0 = (rowg0 + r0) * E_ + hoff + n;
        const size_t g1 = (rowg0 + r0 + 8) * E_ + hoff + n;
        float2 n0 = *(const float2*)(Ng + g0);
        float2 n1 = *(const float2*)(Ng + g1);
        float v00 = acc_o[nf][0] * inv0 + NSCALE * n0.x;
        float v01 = acc_o[nf][1] * inv0 + NSCALE * n0.y;
        float v10 = acc_o[nf][2] * inv1 + NSCALE * n1.x;
        float v11 = acc_o[nf][3] * inv1 + NSCALE * n1.y;
        __half h00 = __float2half_rn(v00), h01 = __float2half_rn(v01);
        __half h10 = __float2half_rn(v10), h11 = __float2half_rn(v11);
        *(__half2*)(Ohi + g0) = __halves2half2(h00, h01);
        *(__half2*)(Ohi + g1) = __halves2half2(h10, h11);
        *(__half2*)(Olo + g0) = __halves2half2(
            __float2half_rn(v00 - __half2float(h00)),
            __float2half_rn(v01 - __half2float(h01)));
        *(__half2*)(Olo + g1) = __halves2half2(
            __float2half_rn(v10 - __half2float(h10)),
            __float2half_rn(v11 - __half2float(h11)));
    }
}

// ---------------------------------------------------------------------------
// Launch: 5 launches — convX(3-batch), convW(4-batch), gemmQKV(3-batch),
// attention, output GEMM.
// ---------------------------------------------------------------------------
extern "C" void kernel_launch(void* const* d_in, const int* in_sizes, int n_in,
                              void* d_out, int out_size)
{
    const float* query = (const float*)d_in[0];
    const float* key_t = (const float*)d_in[1];
    const float* value = (const float*)d_in[2];
    const float* Wq    = (const float*)d_in[3];
    const float* bq    = (const float*)d_in[4];
    const float* Wk    = (const float*)d_in[5];
    const float* bk    = (const float*)d_in[6];
    const float* Wv    = (const float*)d_in[7];
    const float* bv    = (const float*)d_in[8];
    const float* Wo    = (const float*)d_in[9];
    const float* bo    = (const float*)d_in[10];
    const float* noise = (const float*)d_in[11];
    float* out = (float*)d_out;

    __half *x0, *x1, *x2, *w0, *w1, *w2, *w3, *qh, *kh, *vh, *ch, *cl;
    cudaGetSymbolAddress((void**)&x0, g_x0);
    cudaGetSymbolAddress((void**)&x1, g_x1);
    cudaGetSymbolAddress((void**)&x2, g_x2);
    cudaGetSymbolAddress((void**)&w0, g_w0);
    cudaGetSymbolAddress((void**)&w1, g_w1);
    cudaGetSymbolAddress((void**)&w2, g_w2);
    cudaGetSymbolAddress((void**)&w3, g_w3);
    cudaGetSymbolAddress((void**)&qh, g_qh);
    cudaGetSymbolAddress((void**)&kh, g_kh);
    cudaGetSymbolAddress((void**)&vh, g_vh);
    cudaGetSymbolAddress((void**)&ch, g_ch);
    cudaGetSymbolAddress((void**)&cl, g_cl);

    cudaFuncSetAttribute(gemm_qkv_kernel,
                         cudaFuncAttributeMaxDynamicSharedMemorySize, GEMM1_SMEM);
    cudaFuncSetAttribute(gemm2_kernel,
                         cudaFuncAttributeMaxDynamicSharedMemorySize, GEMM2_SMEM);
    cudaFuncSetAttribute(attn_mma_kernel,
                         cudaFuncAttributeMaxDynamicSharedMemorySize, ATTN_SMEM);

    const size_t xTot = (size_t)MTOT * E_;
    const size_t wTot = (size_t)E_ * E_;
    const int cX = (int)((xTot / 8 + 255) / 256);
    const int cW = (int)((wTot / 8 + 255) / 256);

    // batched converts
    ConvBatch cbx;
    cbx.in[0] = query; cbx.out[0] = x0;
    cbx.in[1] = key_t; cbx.out[1] = x1;
    cbx.in[2] = value; cbx.out[2] = x2;
    cbx.in[3] = nullptr; cbx.out[3] = nullptr;
    convert_batch<<<dim3(cX, 3), 256>>>(cbx, xTot);

    ConvBatch cbw;
    cbw.in[0] = Wq; cbw.out[0] = w0;
    cbw.in[1] = Wk; cbw.out[1] = w1;
    cbw.in[2] = Wv; cbw.out[2] = w2;
    cbw.in[3] = Wo; cbw.out[3] = w3;
    convert_batch<<<dim3(cW, 4), 256>>>(cbw, wTot);

    // batched QKV projections
    QKVBatch qp;
    qp.X[0] = x0; qp.W[0] = w0; qp.bias[0] = bq; qp.out[0] = qh;
    qp.X[1] = x1; qp.W[1] = w1; qp.bias[1] = bk; qp.out[1] = kh;
    qp.X[2] = x2; qp.W[2] = w2; qp.bias[2] = bv; qp.out[2] = vh;
    gemm_qkv_kernel<<<dim3(E_ / 128, MTOT / 128, 3), 256, GEMM1_SMEM>>>(qp);

    // Attention + DP noise -> ctx hi/lo
    dim3 attnGrid(S_ / 128, H_, B_);       // (16, 16, 4)
    attn_mma_kernel<<<attnGrid, 256, ATTN_SMEM>>>(qh, kh, vh, noise, ch, cl);

    // out = ctx @ Wo^T + bo
    gemm2_kernel<<<dim3(E_ / 128, MTOT / 128), 256, GEMM2_SMEM>>>(ch, cl, w3, bo, out);
}